// round 12
// baseline (speedup 1.0000x reference)
#include <cuda_runtime.h>
#include <math.h>
#include <stdint.h>

#define LR_H 360
#define LR_W 640
#define HR_H 720
#define HR_W 1280
#define HW_LR (LR_H*LR_W)
#define HW_HR (HR_H*HR_W)

// Scratch (allocation-free rule: __device__ globals)
__device__ float g_amp[64 * HW_LR];   // LR amplitude conv output (with bias)
__device__ float g_x0 [64 * HW_HR];   // up_amp * fourier (MLP input)

// ---------------------------------------------------------------------------
// Neumaier / TwoSum compensated accumulation
// ---------------------------------------------------------------------------
__device__ __forceinline__ void two_sum_acc(float& acc, float& cmp, float t) {
    float s  = __fadd_rn(acc, t);
    float bp = __fsub_rn(s, acc);
    float e  = __fadd_rn(__fsub_rn(acc, __fsub_rn(s, bp)), __fsub_rn(t, bp));
    cmp = __fadd_rn(cmp, e);
    acc = s;
}

// ---------------------------------------------------------------------------
// Accurate sin/cos: Cody-Waite 3-constant pi/2 reduction + cephes minimax.
// ---------------------------------------------------------------------------
__device__ __forceinline__ void red_quad(float x, float& r, int& q) {
    float j = rintf(__fmul_rn(x, 0.636619772367581343f));
    float t = __fmaf_rn(j, -1.57079625129699707031f, x);
    t = __fmaf_rn(j, -7.54978941586015625e-8f, t);
    t = __fmaf_rn(j, -5.39030252995776476554e-15f, t);
    r = t;
    q = ((int)j) & 3;
}
__device__ __forceinline__ float sin_poly(float r, float z) {
    float p = __fmaf_rn(z, -1.9515295891e-4f, 8.3321608736e-3f);
    p = __fmaf_rn(z, p, -1.6666654611e-1f);
    return __fmaf_rn(__fmul_rn(z, r), p, r);
}
__device__ __forceinline__ float cos_poly(float z) {
    float p = __fmaf_rn(z, 2.443315711809948e-5f, -1.388731625493765e-3f);
    p = __fmaf_rn(z, p, 4.166664568298827e-2f);
    return __fmaf_rn(__fmul_rn(z, z), p, __fmaf_rn(z, -0.5f, 1.0f));
}
__device__ __forceinline__ float acc_sinf(float x) {
    float r; int q;
    red_quad(x, r, q);
    float z = __fmul_rn(r, r);
    float sr = sin_poly(r, z), cr = cos_poly(z);
    float v = ((q & 1) == 0) ? sr : cr;
    return ((q & 2) == 0) ? v : -v;
}
__device__ __forceinline__ void acc_sincosf(float x, float& s, float& c) {
    float r; int q;
    red_quad(x, r, q);
    float z = __fmul_rn(r, r);
    float sr = sin_poly(r, z), cr = cos_poly(z);
    float ss, cc;
    if ((q & 1) == 0) { ss = sr; cc = cr; } else { ss = cr; cc = -sr; }
    if (q & 2) { ss = -ss; cc = -cc; }
    s = ss; c = cc;
}

// ---------------------------------------------------------------------------
// K1: LR 3x3 conv 32->64 (+bias) -> g_amp.  Compensated accumulation.
// ---------------------------------------------------------------------------
__global__ __launch_bounds__(256, 2) void k_conv_lr(
    const float* __restrict__ x, const float* __restrict__ w,
    const float* __restrict__ b)
{
    __shared__ float s_t[8 * 10 * 34];
    __shared__ float s_w[8 * 32 * 12];
    const int tid = threadIdx.x, tx = tid & 31, ty = tid >> 5;
    const int bx = blockIdx.x * 32, by = blockIdx.y * 8;
    const int p = (by + ty) * LR_W + bx + tx;

    for (int pass = 0; pass < 2; pass++) {
        float acc[32], cmp[32];
#pragma unroll
        for (int i = 0; i < 32; i++) { acc[i] = 0.f; cmp[i] = 0.f; }

        for (int c0 = 0; c0 < 32; c0 += 8) {
            __syncthreads();
            for (int i = tid; i < 8 * 10 * 34; i += 256) {
                int ci = i / 340, r = (i - ci * 340) / 34, c = i - ci * 340 - r * 34;
                int yy = by + r - 1, xx = bx + c - 1;
                float v = 0.f;
                if (yy >= 0 && yy < LR_H && xx >= 0 && xx < LR_W)
                    v = x[(c0 + ci) * HW_LR + yy * LR_W + xx];
                s_t[i] = v;
            }
            for (int i = tid; i < 8 * 32 * 9; i += 256) {
                int ci = i / 288, r = i - ci * 288, co = r / 9, k = r - co * 9;
                s_w[(ci * 32 + co) * 12 + k] =
                    w[((pass * 32 + co) * 32 + c0 + ci) * 9 + k];
            }
            __syncthreads();
            for (int ci = 0; ci < 8; ci++) {
                const float* tp = &s_t[ci * 340 + ty * 34 + tx];
                float v0 = tp[0],  v1 = tp[1],  v2 = tp[2];
                float v3 = tp[34], v4 = tp[35], v5 = tp[36];
                float v6 = tp[68], v7 = tp[69], v8 = tp[70];
#pragma unroll
                for (int co = 0; co < 32; co++) {
                    const float4* wp = (const float4*)&s_w[(ci * 32 + co) * 12];
                    float4 wa = wp[0], wb = wp[1], wc = wp[2];
                    float t = __fmul_rn(wa.x, v0);
                    t = __fmaf_rn(wa.y, v1, t); t = __fmaf_rn(wa.z, v2, t);
                    t = __fmaf_rn(wa.w, v3, t); t = __fmaf_rn(wb.x, v4, t);
                    t = __fmaf_rn(wb.y, v5, t); t = __fmaf_rn(wb.z, v6, t);
                    t = __fmaf_rn(wb.w, v7, t); t = __fmaf_rn(wc.x, v8, t);
                    two_sum_acc(acc[co], cmp[co], t);
                }
            }
        }
#pragma unroll
        for (int co = 0; co < 32; co++)
            g_amp[(pass * 32 + co) * HW_LR + p] =
                __fadd_rn(__fadd_rn(acc[co], cmp[co]), b[pass * 32 + co]);
    }
}

// ---------------------------------------------------------------------------
// K2: HR 3x3 conv (compensated) -> f -> fourier*up_amp -> g_x0.
// Grid math: XLA reciprocal-multiply rewrite (x/c -> x*(1/c)) hypothesis.
// ---------------------------------------------------------------------------
__global__ __launch_bounds__(256, 2) void k_freq_hr(
    const float* __restrict__ x, const float* __restrict__ w,
    const float* __restrict__ b, const float* __restrict__ phase_w,
    const void* __restrict__ upf)
{
    __shared__ float s_t[8 * 10 * 34];
    __shared__ float s_w[8 * 32 * 12];
    const int tid = threadIdx.x, tx = tid & 31, ty = tid >> 5;
    const int bx = blockIdx.x * 32, by = blockIdx.y * 8;

    const int gx = bx + tx, gy = by + ty;

    // --- XLA-style fp32 grid math with x/c -> x*(1/c) rewrite ---
    const float R720  = (float)(1.0 / 720.0);
    const float R1280 = (float)(1.0 / 1280.0);
    const float R360  = (float)(1.0 / 360.0);
    const float R640  = (float)(1.0 / 640.0);

    // gy = ((g+0.5)*R720)*2 - 1   (mul by 2 exact; single-rounded sub)
    float gyf = __fadd_rn(__fmul_rn(__fmul_rn(__fadd_rn((float)gy, 0.5f), R720),
                                    2.0f), -1.0f);
    float gxf = __fadd_rn(__fmul_rn(__fmul_rn(__fadd_rn((float)gx, 0.5f), R1280),
                                    2.0f), -1.0f);
    // indices: provably g>>1 under both div and recip formulas (margin 0.25)
    const int iy = gy >> 1, ix = gx >> 1;
    // qy = ((iy+0.5)*R360)*2 - 1
    float qy = __fadd_rn(__fmul_rn(__fmul_rn(__fadd_rn((float)iy, 0.5f), R360),
                                   2.0f), -1.0f);
    float qx = __fadd_rn(__fmul_rn(__fmul_rn(__fadd_rn((float)ix, 0.5f), R640),
                                   2.0f), -1.0f);
    float rely = __fmul_rn(__fsub_rn(gyf, qy), (float)LR_H);
    float relx = __fmul_rn(__fsub_rn(gxf, qx), (float)LR_W);

    const int q = iy * LR_W + ix;
    const int p = gy * HR_W + gx;

    int iv = *(const int*)upf;
    float s_up = (iv > 0 && iv < 100000) ? (float)iv : __int_as_float(iv);
    float inv_s = __fdiv_rn(1.0f, s_up);
    const float PI_F = 3.14159265358979323846f;

    for (int pass = 0; pass < 2; pass++) {
        float acc[32], cmp[32];
#pragma unroll
        for (int i = 0; i < 32; i++) { acc[i] = 0.f; cmp[i] = 0.f; }

        for (int c0 = 0; c0 < 32; c0 += 8) {
            __syncthreads();
            for (int i = tid; i < 8 * 10 * 34; i += 256) {
                int ci = i / 340, r = (i - ci * 340) / 34, c = i - ci * 340 - r * 34;
                int yy = by + r - 1, xx = bx + c - 1;
                float v = 0.f;
                if (yy >= 0 && yy < HR_H && xx >= 0 && xx < HR_W)
                    v = x[(c0 + ci) * HW_HR + yy * HR_W + xx];
                s_t[i] = v;
            }
            for (int i = tid; i < 8 * 32 * 9; i += 256) {
                int ci = i / 288, r = i - ci * 288, co = r / 9, k = r - co * 9;
                s_w[(ci * 32 + co) * 12 + k] =
                    w[((pass * 32 + co) * 32 + c0 + ci) * 9 + k];
            }
            __syncthreads();
            for (int ci = 0; ci < 8; ci++) {
                const float* tp = &s_t[ci * 340 + ty * 34 + tx];
                float v0 = tp[0],  v1 = tp[1],  v2 = tp[2];
                float v3 = tp[34], v4 = tp[35], v5 = tp[36];
                float v6 = tp[68], v7 = tp[69], v8 = tp[70];
#pragma unroll
                for (int co = 0; co < 32; co++) {
                    const float4* wp = (const float4*)&s_w[(ci * 32 + co) * 12];
                    float4 wa = wp[0], wb = wp[1], wc = wp[2];
                    float t = __fmul_rn(wa.x, v0);
                    t = __fmaf_rn(wa.y, v1, t); t = __fmaf_rn(wa.z, v2, t);
                    t = __fmaf_rn(wa.w, v3, t); t = __fmaf_rn(wb.x, v4, t);
                    t = __fmaf_rn(wb.y, v5, t); t = __fmaf_rn(wb.z, v6, t);
                    t = __fmaf_rn(wb.w, v7, t); t = __fmaf_rn(wc.x, v8, t);
                    two_sum_acc(acc[co], cmp[co], t);
                }
            }
        }

#pragma unroll
        for (int cl = 0; cl < 16; cl++) {
            int c = pass * 16 + cl;
            float fy = __fadd_rn(__fadd_rn(acc[2 * cl],     cmp[2 * cl]),
                                 b[2 * c]);
            float fx = __fadd_rn(__fadd_rn(acc[2 * cl + 1], cmp[2 * cl + 1]),
                                 b[2 * c + 1]);
            float f = __fadd_rn(__fadd_rn(__fmul_rn(fy, rely),
                                          __fmul_rn(fx, relx)),
                                __fmul_rn(phase_w[c], inv_s));
            float sv, cv;
            acc_sincosf(__fmul_rn(PI_F, f), sv, cv);
            g_x0[c * HW_HR + p]        = __fmul_rn(g_amp[c * HW_LR + q],        cv);
            g_x0[(c + 32) * HW_HR + p] = __fmul_rn(g_amp[(c + 32) * HW_LR + q], sv);
        }
    }
}

// ---------------------------------------------------------------------------
// K3: per-pixel MLP with compensated dots: 3x (64->64, sin(30*)) then 64->12.
// ---------------------------------------------------------------------------
#define ROWSTR 132
#define K3_SMEM_BYTES ((3*4096 + 768 + 208 + 256*ROWSTR) * 4)

__global__ __launch_bounds__(256) void k_mlp(
    const float* __restrict__ w0, const float* __restrict__ b0,
    const float* __restrict__ w1, const float* __restrict__ b1,
    const float* __restrict__ w2, const float* __restrict__ b2,
    const float* __restrict__ wo, const float* __restrict__ bo,
    float* __restrict__ out)
{
    extern __shared__ float sm[];
    float* s_w  = sm;
    float* s_wo = sm + 3 * 4096;
    float* s_b  = s_wo + 768;
    float* s_px = s_b + 208;

    const int tid = threadIdx.x;
    for (int i = tid; i < 4096; i += 256) {
        s_w[i] = w0[i]; s_w[4096 + i] = w1[i]; s_w[8192 + i] = w2[i];
    }
    for (int i = tid; i < 768; i += 256) s_wo[i] = wo[i];
    if (tid < 64) { s_b[tid] = b0[tid]; s_b[64 + tid] = b1[tid]; s_b[128 + tid] = b2[tid]; }
    if (tid < 12) s_b[192 + tid] = bo[tid];
    __syncthreads();

    const int p = blockIdx.x * 256 + tid;
    float* row = s_px + tid * ROWSTR;

#pragma unroll
    for (int c = 0; c < 64; c++) row[c] = g_x0[c * HW_HR + p];

    int xo = 0;
#pragma unroll
    for (int L = 0; L < 3; L++) {
        const float* wl = s_w + L * 4096;
        const float* bl = s_b + L * 64;
        int yo = 64 - xo;
        const float4* xr = (const float4*)(row + xo);
        for (int ob = 0; ob < 8; ob++) {
            float a[8], ac[8];
#pragma unroll
            for (int oo = 0; oo < 8; oo++) { a[oo] = 0.f; ac[oo] = 0.f; }
            const float* wb = wl + ob * 8 * 64;
#pragma unroll
            for (int ch = 0; ch < 4; ch++) {
                float4 xv0 = xr[ch * 4 + 0], xv1 = xr[ch * 4 + 1];
                float4 xv2 = xr[ch * 4 + 2], xv3 = xr[ch * 4 + 3];
#pragma unroll
                for (int oo = 0; oo < 8; oo++) {
                    const float4* wp = (const float4*)(wb + oo * 64 + ch * 16);
                    float4 wq0 = wp[0], wq1 = wp[1], wq2 = wp[2], wq3 = wp[3];
                    float t = __fmul_rn(wq0.x, xv0.x);
                    t = __fmaf_rn(wq0.y, xv0.y, t);
                    t = __fmaf_rn(wq0.z, xv0.z, t); t = __fmaf_rn(wq0.w, xv0.w, t);
                    t = __fmaf_rn(wq1.x, xv1.x, t); t = __fmaf_rn(wq1.y, xv1.y, t);
                    t = __fmaf_rn(wq1.z, xv1.z, t); t = __fmaf_rn(wq1.w, xv1.w, t);
                    t = __fmaf_rn(wq2.x, xv2.x, t); t = __fmaf_rn(wq2.y, xv2.y, t);
                    t = __fmaf_rn(wq2.z, xv2.z, t); t = __fmaf_rn(wq2.w, xv2.w, t);
                    t = __fmaf_rn(wq3.x, xv3.x, t); t = __fmaf_rn(wq3.y, xv3.y, t);
                    t = __fmaf_rn(wq3.z, xv3.z, t); t = __fmaf_rn(wq3.w, xv3.w, t);
                    two_sum_acc(a[oo], ac[oo], t);
                }
            }
#pragma unroll
            for (int oo = 0; oo < 8; oo++) {
                float u = __fadd_rn(__fadd_rn(a[oo], ac[oo]), bl[ob * 8 + oo]);
                row[yo + ob * 8 + oo] = acc_sinf(__fmul_rn(30.0f, u));
            }
        }
        xo = yo;
    }

    const float4* xr = (const float4*)(row + xo);
    for (int o = 0; o < 12; o++) {
        float acc = s_b[192 + o];
        const float4* wp = (const float4*)(s_wo + o * 64);
#pragma unroll
        for (int qq = 0; qq < 16; qq++) {
            float4 wv = wp[qq];
            float4 xv = xr[qq];
            acc = __fmaf_rn(wv.x, xv.x, acc); acc = __fmaf_rn(wv.y, xv.y, acc);
            acc = __fmaf_rn(wv.z, xv.z, acc); acc = __fmaf_rn(wv.w, xv.w, acc);
        }
        out[o * HW_HR + p] = acc;
    }
}

// ---------------------------------------------------------------------------
extern "C" void kernel_launch(void* const* d_in, const int* in_sizes, int n_in,
                              void* d_out, int out_size)
{
    const float* lr_feat = (const float*)d_in[0];
    const float* gb_feat = (const float*)d_in[1];
    const float* amp_w   = (const float*)d_in[2];
    const float* amp_b   = (const float*)d_in[3];
    const float* freq_w  = (const float*)d_in[4];
    const float* freq_b  = (const float*)d_in[5];
    const float* phase_w = (const float*)d_in[6];
    const float* w0      = (const float*)d_in[7];
    const float* b0      = (const float*)d_in[8];
    const float* w1      = (const float*)d_in[9];
    const float* b1      = (const float*)d_in[10];
    const float* w2      = (const float*)d_in[11];
    const float* b2      = (const float*)d_in[12];
    const float* wo      = (const float*)d_in[13];
    const float* bo      = (const float*)d_in[14];
    const void*  upf     = d_in[15];

    cudaFuncSetAttribute(k_mlp, cudaFuncAttributeMaxDynamicSharedMemorySize,
                         K3_SMEM_BYTES);

    k_conv_lr<<<dim3(LR_W / 32, LR_H / 8), 256>>>(lr_feat, amp_w, amp_b);
    k_freq_hr<<<dim3(HR_W / 32, HR_H / 8), 256>>>(gb_feat, freq_w, freq_b,
                                                  phase_w, upf);
    k_mlp<<<HW_HR / 256, 256, K3_SMEM_BYTES>>>(w0, b0, w1, b1, w2, b2, wo, bo,
                                               (float*)d_out);
}

// round 13
// speedup vs baseline: 1.0510x; 1.0510x over previous
#include <cuda_runtime.h>
#include <math.h>
#include <stdint.h>

#define LR_H 360
#define LR_W 640
#define HR_H 720
#define HR_W 1280
#define HW_LR (LR_H*LR_W)
#define HW_HR (HR_H*HR_W)

// Scratch (allocation-free rule: __device__ globals)
__device__ float g_amp[64 * HW_LR];   // LR amplitude conv output (with bias)
__device__ float g_x0 [64 * HW_HR];   // up_amp * fourier (MLP input)

// ---------------------------------------------------------------------------
// Accurate sin/cos: Cody-Waite 3-constant pi/2 reduction + cephes minimax.
// ---------------------------------------------------------------------------
__device__ __forceinline__ void red_quad(float x, float& r, int& q) {
    float j = rintf(__fmul_rn(x, 0.636619772367581343f));
    float t = __fmaf_rn(j, -1.57079625129699707031f, x);
    t = __fmaf_rn(j, -7.54978941586015625e-8f, t);
    t = __fmaf_rn(j, -5.39030252995776476554e-15f, t);
    r = t;
    q = ((int)j) & 3;
}
__device__ __forceinline__ float sin_poly(float r, float z) {
    float p = __fmaf_rn(z, -1.9515295891e-4f, 8.3321608736e-3f);
    p = __fmaf_rn(z, p, -1.6666654611e-1f);
    return __fmaf_rn(__fmul_rn(z, r), p, r);
}
__device__ __forceinline__ float cos_poly(float z) {
    float p = __fmaf_rn(z, 2.443315711809948e-5f, -1.388731625493765e-3f);
    p = __fmaf_rn(z, p, 4.166664568298827e-2f);
    return __fmaf_rn(__fmul_rn(z, z), p, __fmaf_rn(z, -0.5f, 1.0f));
}
__device__ __forceinline__ float acc_sinf(float x) {
    float r; int q;
    red_quad(x, r, q);
    float z = __fmul_rn(r, r);
    float sr = sin_poly(r, z), cr = cos_poly(z);
    float v = ((q & 1) == 0) ? sr : cr;
    return ((q & 2) == 0) ? v : -v;
}
__device__ __forceinline__ void acc_sincosf(float x, float& s, float& c) {
    float r; int q;
    red_quad(x, r, q);
    float z = __fmul_rn(r, r);
    float sr = sin_poly(r, z), cr = cos_poly(z);
    float ss, cc;
    if ((q & 1) == 0) { ss = sr; cc = cr; } else { ss = cr; cc = -sr; }
    if (q & 2) { ss = -ss; cc = -cc; }
    s = ss; c = cc;
}

// ---------------------------------------------------------------------------
// K1: LR 3x3 conv 32->64 (+bias) -> g_amp.  Plain fp32 FMA, single pass.
// ---------------------------------------------------------------------------
__global__ __launch_bounds__(256, 2) void k_conv_lr(
    const float* __restrict__ x, const float* __restrict__ w,
    const float* __restrict__ b)
{
    __shared__ float s_t[8 * 10 * 34];   // 8 ci x (8+2) rows x (32+2) cols
    __shared__ float s_w[8 * 64 * 12];   // [ci][co][12] (9 used)
    const int tid = threadIdx.x, tx = tid & 31, ty = tid >> 5;
    const int bx = blockIdx.x * 32, by = blockIdx.y * 8;

    float acc[64];
#pragma unroll
    for (int i = 0; i < 64; i++) acc[i] = 0.f;

    for (int c0 = 0; c0 < 32; c0 += 8) {
        __syncthreads();
        for (int i = tid; i < 8 * 10 * 34; i += 256) {
            int ci = i / 340, r = (i - ci * 340) / 34, c = i - ci * 340 - r * 34;
            int yy = by + r - 1, xx = bx + c - 1;
            float v = 0.f;
            if (yy >= 0 && yy < LR_H && xx >= 0 && xx < LR_W)
                v = x[(c0 + ci) * HW_LR + yy * LR_W + xx];
            s_t[i] = v;
        }
        for (int i = tid; i < 8 * 64 * 9; i += 256) {
            int ci = i / 576, r = i - ci * 576, co = r / 9, k = r - co * 9;
            s_w[(ci * 64 + co) * 12 + k] = w[(co * 32 + c0 + ci) * 9 + k];
        }
        __syncthreads();
        for (int ci = 0; ci < 8; ci++) {
            const float* tp = &s_t[ci * 340 + ty * 34 + tx];
            float v0 = tp[0],  v1 = tp[1],  v2 = tp[2];
            float v3 = tp[34], v4 = tp[35], v5 = tp[36];
            float v6 = tp[68], v7 = tp[69], v8 = tp[70];
#pragma unroll
            for (int co = 0; co < 64; co++) {
                const float4* wp = (const float4*)&s_w[(ci * 64 + co) * 12];
                float4 wa = wp[0], wb = wp[1], wc = wp[2];
                float t = acc[co];
                t = __fmaf_rn(wa.x, v0, t); t = __fmaf_rn(wa.y, v1, t);
                t = __fmaf_rn(wa.z, v2, t); t = __fmaf_rn(wa.w, v3, t);
                t = __fmaf_rn(wb.x, v4, t); t = __fmaf_rn(wb.y, v5, t);
                t = __fmaf_rn(wb.z, v6, t); t = __fmaf_rn(wb.w, v7, t);
                t = __fmaf_rn(wc.x, v8, t);
                acc[co] = t;
            }
        }
    }
    int p = (by + ty) * LR_W + bx + tx;
#pragma unroll
    for (int co = 0; co < 64; co++)
        g_amp[co * HW_LR + p] = __fadd_rn(acc[co], b[co]);
}

// ---------------------------------------------------------------------------
// K2: HR 3x3 conv 32->64 -> f -> fourier*up_amp -> g_x0.  Plain fp32,
// single pass.  Grid math: XLA reciprocal-multiply rewrite (VALIDATED R12).
// ---------------------------------------------------------------------------
__global__ __launch_bounds__(256, 2) void k_freq_hr(
    const float* __restrict__ x, const float* __restrict__ w,
    const float* __restrict__ b, const float* __restrict__ phase_w,
    const void* __restrict__ upf)
{
    __shared__ float s_t[8 * 10 * 34];
    __shared__ float s_w[8 * 64 * 12];
    const int tid = threadIdx.x, tx = tid & 31, ty = tid >> 5;
    const int bx = blockIdx.x * 32, by = blockIdx.y * 8;

    float acc[64];
#pragma unroll
    for (int i = 0; i < 64; i++) acc[i] = 0.f;

    for (int c0 = 0; c0 < 32; c0 += 8) {
        __syncthreads();
        for (int i = tid; i < 8 * 10 * 34; i += 256) {
            int ci = i / 340, r = (i - ci * 340) / 34, c = i - ci * 340 - r * 34;
            int yy = by + r - 1, xx = bx + c - 1;
            float v = 0.f;
            if (yy >= 0 && yy < HR_H && xx >= 0 && xx < HR_W)
                v = x[(c0 + ci) * HW_HR + yy * HR_W + xx];
            s_t[i] = v;
        }
        for (int i = tid; i < 8 * 64 * 9; i += 256) {
            int ci = i / 576, r = i - ci * 576, co = r / 9, k = r - co * 9;
            s_w[(ci * 64 + co) * 12 + k] = w[(co * 32 + c0 + ci) * 9 + k];
        }
        __syncthreads();
        for (int ci = 0; ci < 8; ci++) {
            const float* tp = &s_t[ci * 340 + ty * 34 + tx];
            float v0 = tp[0],  v1 = tp[1],  v2 = tp[2];
            float v3 = tp[34], v4 = tp[35], v5 = tp[36];
            float v6 = tp[68], v7 = tp[69], v8 = tp[70];
#pragma unroll
            for (int co = 0; co < 64; co++) {
                const float4* wp = (const float4*)&s_w[(ci * 64 + co) * 12];
                float4 wa = wp[0], wb = wp[1], wc = wp[2];
                float t = acc[co];
                t = __fmaf_rn(wa.x, v0, t); t = __fmaf_rn(wa.y, v1, t);
                t = __fmaf_rn(wa.z, v2, t); t = __fmaf_rn(wa.w, v3, t);
                t = __fmaf_rn(wb.x, v4, t); t = __fmaf_rn(wb.y, v5, t);
                t = __fmaf_rn(wb.z, v6, t); t = __fmaf_rn(wb.w, v7, t);
                t = __fmaf_rn(wc.x, v8, t);
                acc[co] = t;
            }
        }
    }

    // --- XLA-style fp32 grid math with x/c -> x*(1/c) rewrite (R12) ---
    const int gx = bx + tx, gy = by + ty;
    const float R720  = (float)(1.0 / 720.0);
    const float R1280 = (float)(1.0 / 1280.0);
    const float R360  = (float)(1.0 / 360.0);
    const float R640  = (float)(1.0 / 640.0);

    float gyf = __fadd_rn(__fmul_rn(__fmul_rn(__fadd_rn((float)gy, 0.5f), R720),
                                    2.0f), -1.0f);
    float gxf = __fadd_rn(__fmul_rn(__fmul_rn(__fadd_rn((float)gx, 0.5f), R1280),
                                    2.0f), -1.0f);
    const int iy = gy >> 1, ix = gx >> 1;
    float qy = __fadd_rn(__fmul_rn(__fmul_rn(__fadd_rn((float)iy, 0.5f), R360),
                                   2.0f), -1.0f);
    float qx = __fadd_rn(__fmul_rn(__fmul_rn(__fadd_rn((float)ix, 0.5f), R640),
                                   2.0f), -1.0f);
    float rely = __fmul_rn(__fsub_rn(gyf, qy), (float)LR_H);
    float relx = __fmul_rn(__fsub_rn(gxf, qx), (float)LR_W);

    const int q = iy * LR_W + ix;
    const int p = gy * HR_W + gx;

    int iv = *(const int*)upf;
    float s_up = (iv > 0 && iv < 100000) ? (float)iv : __int_as_float(iv);
    float inv_s = __fdiv_rn(1.0f, s_up);
    const float PI_F = 3.14159265358979323846f;

#pragma unroll
    for (int c = 0; c < 32; c++) {
        float fy = __fadd_rn(acc[2 * c],     b[2 * c]);
        float fx = __fadd_rn(acc[2 * c + 1], b[2 * c + 1]);
        float f = __fadd_rn(__fadd_rn(__fmul_rn(fy, rely),
                                      __fmul_rn(fx, relx)),
                            __fmul_rn(phase_w[c], inv_s));
        float sv, cv;
        acc_sincosf(__fmul_rn(PI_F, f), sv, cv);
        g_x0[c * HW_HR + p]        = __fmul_rn(g_amp[c * HW_LR + q],        cv);
        g_x0[(c + 32) * HW_HR + p] = __fmul_rn(g_amp[(c + 32) * HW_LR + q], sv);
    }
}

// ---------------------------------------------------------------------------
// K3: per-pixel MLP, plain fp32: 3x (64->64, sin(30*)) then 64->12.
// ---------------------------------------------------------------------------
#define ROWSTR 132
#define K3_SMEM_BYTES ((3*4096 + 768 + 208 + 256*ROWSTR) * 4)

__global__ __launch_bounds__(256) void k_mlp(
    const float* __restrict__ w0, const float* __restrict__ b0,
    const float* __restrict__ w1, const float* __restrict__ b1,
    const float* __restrict__ w2, const float* __restrict__ b2,
    const float* __restrict__ wo, const float* __restrict__ bo,
    float* __restrict__ out)
{
    extern __shared__ float sm[];
    float* s_w  = sm;
    float* s_wo = sm + 3 * 4096;
    float* s_b  = s_wo + 768;
    float* s_px = s_b + 208;

    const int tid = threadIdx.x;
    for (int i = tid; i < 4096; i += 256) {
        s_w[i] = w0[i]; s_w[4096 + i] = w1[i]; s_w[8192 + i] = w2[i];
    }
    for (int i = tid; i < 768; i += 256) s_wo[i] = wo[i];
    if (tid < 64) { s_b[tid] = b0[tid]; s_b[64 + tid] = b1[tid]; s_b[128 + tid] = b2[tid]; }
    if (tid < 12) s_b[192 + tid] = bo[tid];
    __syncthreads();

    const int p = blockIdx.x * 256 + tid;
    float* row = s_px + tid * ROWSTR;

#pragma unroll
    for (int c = 0; c < 64; c++) row[c] = g_x0[c * HW_HR + p];

    int xo = 0;
#pragma unroll
    for (int L = 0; L < 3; L++) {
        const float* wl = s_w + L * 4096;
        const float* bl = s_b + L * 64;
        int yo = 64 - xo;
        const float4* xr = (const float4*)(row + xo);
        for (int ob = 0; ob < 8; ob++) {
            float a[8];
#pragma unroll
            for (int oo = 0; oo < 8; oo++) a[oo] = bl[ob * 8 + oo];
            const float* wb = wl + ob * 8 * 64;
#pragma unroll
            for (int ch = 0; ch < 4; ch++) {
                float4 xv0 = xr[ch * 4 + 0], xv1 = xr[ch * 4 + 1];
                float4 xv2 = xr[ch * 4 + 2], xv3 = xr[ch * 4 + 3];
#pragma unroll
                for (int oo = 0; oo < 8; oo++) {
                    const float4* wp = (const float4*)(wb + oo * 64 + ch * 16);
                    float4 wq0 = wp[0], wq1 = wp[1], wq2 = wp[2], wq3 = wp[3];
                    float t = a[oo];
                    t = __fmaf_rn(wq0.x, xv0.x, t); t = __fmaf_rn(wq0.y, xv0.y, t);
                    t = __fmaf_rn(wq0.z, xv0.z, t); t = __fmaf_rn(wq0.w, xv0.w, t);
                    t = __fmaf_rn(wq1.x, xv1.x, t); t = __fmaf_rn(wq1.y, xv1.y, t);
                    t = __fmaf_rn(wq1.z, xv1.z, t); t = __fmaf_rn(wq1.w, xv1.w, t);
                    t = __fmaf_rn(wq2.x, xv2.x, t); t = __fmaf_rn(wq2.y, xv2.y, t);
                    t = __fmaf_rn(wq2.z, xv2.z, t); t = __fmaf_rn(wq2.w, xv2.w, t);
                    t = __fmaf_rn(wq3.x, xv3.x, t); t = __fmaf_rn(wq3.y, xv3.y, t);
                    t = __fmaf_rn(wq3.z, xv3.z, t); t = __fmaf_rn(wq3.w, xv3.w, t);
                    a[oo] = t;
                }
            }
#pragma unroll
            for (int oo = 0; oo < 8; oo++)
                row[yo + ob * 8 + oo] = acc_sinf(__fmul_rn(30.0f, a[oo]));
        }
        xo = yo;
    }

    const float4* xr = (const float4*)(row + xo);
    for (int o = 0; o < 12; o++) {
        float acc = s_b[192 + o];
        const float4* wp = (const float4*)(s_wo + o * 64);
#pragma unroll
        for (int qq = 0; qq < 16; qq++) {
            float4 wv = wp[qq];
            float4 xv = xr[qq];
            acc = __fmaf_rn(wv.x, xv.x, acc); acc = __fmaf_rn(wv.y, xv.y, acc);
            acc = __fmaf_rn(wv.z, xv.z, acc); acc = __fmaf_rn(wv.w, xv.w, acc);
        }
        out[o * HW_HR + p] = acc;
    }
}

// ---------------------------------------------------------------------------
extern "C" void kernel_launch(void* const* d_in, const int* in_sizes, int n_in,
                              void* d_out, int out_size)
{
    const float* lr_feat = (const float*)d_in[0];
    const float* gb_feat = (const float*)d_in[1];
    const float* amp_w   = (const float*)d_in[2];
    const float* amp_b   = (const float*)d_in[3];
    const float* freq_w  = (const float*)d_in[4];
    const float* freq_b  = (const float*)d_in[5];
    const float* phase_w = (const float*)d_in[6];
    const float* w0      = (const float*)d_in[7];
    const float* b0      = (const float*)d_in[8];
    const float* w1      = (const float*)d_in[9];
    const float* b1      = (const float*)d_in[10];
    const float* w2      = (const float*)d_in[11];
    const float* b2      = (const float*)d_in[12];
    const float* wo      = (const float*)d_in[13];
    const float* bo      = (const float*)d_in[14];
    const void*  upf     = d_in[15];

    cudaFuncSetAttribute(k_mlp, cudaFuncAttributeMaxDynamicSharedMemorySize,
                         K3_SMEM_BYTES);

    k_conv_lr<<<dim3(LR_W / 32, LR_H / 8), 256>>>(lr_feat, amp_w, amp_b);
    k_freq_hr<<<dim3(HR_W / 32, HR_H / 8), 256>>>(gb_feat, freq_w, freq_b,
                                                  phase_w, upf);
    k_mlp<<<HW_HR / 256, 256, K3_SMEM_BYTES>>>(w0, b0, w1, b1, w2, b2, wo, bo,
                                               (float*)d_out);
}

// round 15
// speedup vs baseline: 1.2237x; 1.1643x over previous
#include <cuda_runtime.h>
#include <math.h>
#include <stdint.h>

#define LR_H 360
#define LR_W 640
#define HR_H 720
#define HR_W 1280
#define HW_LR (LR_H*LR_W)
#define HW_HR (HR_H*HR_W)

// Scratch (allocation-free rule: __device__ globals)
__device__ float g_amp[64 * HW_LR];   // LR amplitude conv output (with bias)
__device__ float g_x0 [64 * HW_HR];   // up_amp * fourier (MLP input)

// ---------------------------------------------------------------------------
// Accurate sin/cos: Cody-Waite 3-constant pi/2 reduction + cephes minimax.
// ---------------------------------------------------------------------------
__device__ __forceinline__ void red_quad(float x, float& r, int& q) {
    float j = rintf(__fmul_rn(x, 0.636619772367581343f));
    float t = __fmaf_rn(j, -1.57079625129699707031f, x);
    t = __fmaf_rn(j, -7.54978941586015625e-8f, t);
    t = __fmaf_rn(j, -5.39030252995776476554e-15f, t);
    r = t;
    q = ((int)j) & 3;
}
__device__ __forceinline__ float sin_poly(float r, float z) {
    float p = __fmaf_rn(z, -1.9515295891e-4f, 8.3321608736e-3f);
    p = __fmaf_rn(z, p, -1.6666654611e-1f);
    return __fmaf_rn(__fmul_rn(z, r), p, r);
}
__device__ __forceinline__ float cos_poly(float z) {
    float p = __fmaf_rn(z, 2.443315711809948e-5f, -1.388731625493765e-3f);
    p = __fmaf_rn(z, p, 4.166664568298827e-2f);
    return __fmaf_rn(__fmul_rn(z, z), p, __fmaf_rn(z, -0.5f, 1.0f));
}
__device__ __forceinline__ float acc_sinf(float x) {
    float r; int q;
    red_quad(x, r, q);
    float z = __fmul_rn(r, r);
    float sr = sin_poly(r, z), cr = cos_poly(z);
    float v = ((q & 1) == 0) ? sr : cr;
    return ((q & 2) == 0) ? v : -v;
}
__device__ __forceinline__ void acc_sincosf(float x, float& s, float& c) {
    float r; int q;
    red_quad(x, r, q);
    float z = __fmul_rn(r, r);
    float sr = sin_poly(r, z), cr = cos_poly(z);
    float ss, cc;
    if ((q & 1) == 0) { ss = sr; cc = cr; } else { ss = cr; cc = -sr; }
    if (q & 2) { ss = -ss; cc = -cc; }
    s = ss; c = cc;
}

// ---------------------------------------------------------------------------
// K1: LR 3x3 conv 32->64 (+bias) -> g_amp.
// Thread = (pixel in 32x4 tile, co-half). acc[32], high occupancy.
// ---------------------------------------------------------------------------
__global__ __launch_bounds__(256, 4) void k_conv_lr(
    const float* __restrict__ x, const float* __restrict__ w,
    const float* __restrict__ b)
{
    __shared__ float s_t[8 * 6 * 34];    // 8 ci x (4+2) rows x (32+2) cols
    __shared__ float s_w[8 * 64 * 12];   // [ci][co][12] (9 used)
    const int tid = threadIdx.x;
    const int tx = tid & 31, ty = (tid >> 5) & 3, h = tid >> 7;
    const int bx = blockIdx.x * 32, by = blockIdx.y * 4;

    float acc[32];
#pragma unroll
    for (int i = 0; i < 32; i++) acc[i] = 0.f;

    for (int c0 = 0; c0 < 32; c0 += 8) {
        __syncthreads();
        for (int i = tid; i < 8 * 6 * 34; i += 256) {
            int ci = i / 204, rem = i - ci * 204, r = rem / 34, c = rem - r * 34;
            int yy = by + r - 1, xx = bx + c - 1;
            float v = 0.f;
            if (yy >= 0 && yy < LR_H && xx >= 0 && xx < LR_W)
                v = x[(c0 + ci) * HW_LR + yy * LR_W + xx];
            s_t[i] = v;
        }
        for (int i = tid; i < 8 * 64 * 9; i += 256) {
            int ci = i / 576, r = i - ci * 576, co = r / 9, k = r - co * 9;
            s_w[(ci * 64 + co) * 12 + k] = w[(co * 32 + c0 + ci) * 9 + k];
        }
        __syncthreads();
        for (int ci = 0; ci < 8; ci++) {
            const float* tp = &s_t[ci * 204 + ty * 34 + tx];
            float v0 = tp[0],  v1 = tp[1],  v2 = tp[2];
            float v3 = tp[34], v4 = tp[35], v5 = tp[36];
            float v6 = tp[68], v7 = tp[69], v8 = tp[70];
#pragma unroll
            for (int co = 0; co < 32; co++) {
                const float4* wp = (const float4*)&s_w[(ci * 64 + h * 32 + co) * 12];
                float4 wa = wp[0], wb = wp[1], wc = wp[2];
                float t = acc[co];
                t = __fmaf_rn(wa.x, v0, t); t = __fmaf_rn(wa.y, v1, t);
                t = __fmaf_rn(wa.z, v2, t); t = __fmaf_rn(wa.w, v3, t);
                t = __fmaf_rn(wb.x, v4, t); t = __fmaf_rn(wb.y, v5, t);
                t = __fmaf_rn(wb.z, v6, t); t = __fmaf_rn(wb.w, v7, t);
                t = __fmaf_rn(wc.x, v8, t);
                acc[co] = t;
            }
        }
    }
    int p = (by + ty) * LR_W + bx + tx;
#pragma unroll
    for (int co = 0; co < 32; co++)
        g_amp[(h * 32 + co) * HW_LR + p] = __fadd_rn(acc[co], b[h * 32 + co]);
}

// ---------------------------------------------------------------------------
// K2: HR 3x3 conv -> f -> fourier*up_amp -> g_x0.
// Thread = (pixel in 32x4 tile, co-half); each half handles its 16 pairs.
// Grid math: XLA reciprocal-multiply rewrite (VALIDATED R12), verbatim.
// ---------------------------------------------------------------------------
__global__ __launch_bounds__(256, 4) void k_freq_hr(
    const float* __restrict__ x, const float* __restrict__ w,
    const float* __restrict__ b, const float* __restrict__ phase_w,
    const void* __restrict__ upf)
{
    __shared__ float s_t[8 * 6 * 34];
    __shared__ float s_w[8 * 64 * 12];
    const int tid = threadIdx.x;
    const int tx = tid & 31, ty = (tid >> 5) & 3, h = tid >> 7;
    const int bx = blockIdx.x * 32, by = blockIdx.y * 4;

    float acc[32];
#pragma unroll
    for (int i = 0; i < 32; i++) acc[i] = 0.f;

    for (int c0 = 0; c0 < 32; c0 += 8) {
        __syncthreads();
        for (int i = tid; i < 8 * 6 * 34; i += 256) {
            int ci = i / 204, rem = i - ci * 204, r = rem / 34, c = rem - r * 34;
            int yy = by + r - 1, xx = bx + c - 1;
            float v = 0.f;
            if (yy >= 0 && yy < HR_H && xx >= 0 && xx < HR_W)
                v = x[(c0 + ci) * HW_HR + yy * HR_W + xx];
            s_t[i] = v;
        }
        for (int i = tid; i < 8 * 64 * 9; i += 256) {
            int ci = i / 576, r = i - ci * 576, co = r / 9, k = r - co * 9;
            s_w[(ci * 64 + co) * 12 + k] = w[(co * 32 + c0 + ci) * 9 + k];
        }
        __syncthreads();
        for (int ci = 0; ci < 8; ci++) {
            const float* tp = &s_t[ci * 204 + ty * 34 + tx];
            float v0 = tp[0],  v1 = tp[1],  v2 = tp[2];
            float v3 = tp[34], v4 = tp[35], v5 = tp[36];
            float v6 = tp[68], v7 = tp[69], v8 = tp[70];
#pragma unroll
            for (int co = 0; co < 32; co++) {
                const float4* wp = (const float4*)&s_w[(ci * 64 + h * 32 + co) * 12];
                float4 wa = wp[0], wb = wp[1], wc = wp[2];
                float t = acc[co];
                t = __fmaf_rn(wa.x, v0, t); t = __fmaf_rn(wa.y, v1, t);
                t = __fmaf_rn(wa.z, v2, t); t = __fmaf_rn(wa.w, v3, t);
                t = __fmaf_rn(wb.x, v4, t); t = __fmaf_rn(wb.y, v5, t);
                t = __fmaf_rn(wb.z, v6, t); t = __fmaf_rn(wb.w, v7, t);
                t = __fmaf_rn(wc.x, v8, t);
                acc[co] = t;
            }
        }
    }

    // --- XLA-style fp32 grid math with x/c -> x*(1/c) rewrite (R12) ---
    const int gx = bx + tx, gy = by + ty;
    const float R720  = (float)(1.0 / 720.0);
    const float R1280 = (float)(1.0 / 1280.0);
    const float R360  = (float)(1.0 / 360.0);
    const float R640  = (float)(1.0 / 640.0);

    float gyf = __fadd_rn(__fmul_rn(__fmul_rn(__fadd_rn((float)gy, 0.5f), R720),
                                    2.0f), -1.0f);
    float gxf = __fadd_rn(__fmul_rn(__fmul_rn(__fadd_rn((float)gx, 0.5f), R1280),
                                    2.0f), -1.0f);
    const int iy = gy >> 1, ix = gx >> 1;
    float qy = __fadd_rn(__fmul_rn(__fmul_rn(__fadd_rn((float)iy, 0.5f), R360),
                                   2.0f), -1.0f);
    float qx = __fadd_rn(__fmul_rn(__fmul_rn(__fadd_rn((float)ix, 0.5f), R640),
                                   2.0f), -1.0f);
    float rely = __fmul_rn(__fsub_rn(gyf, qy), (float)LR_H);
    float relx = __fmul_rn(__fsub_rn(gxf, qx), (float)LR_W);

    const int q = iy * LR_W + ix;
    const int p = gy * HR_W + gx;

    int iv = *(const int*)upf;
    float s_up = (iv > 0 && iv < 100000) ? (float)iv : __int_as_float(iv);
    float inv_s = __fdiv_rn(1.0f, s_up);
    const float PI_F = 3.14159265358979323846f;

#pragma unroll
    for (int cl = 0; cl < 16; cl++) {
        int c = h * 16 + cl;                       // pair index 0..31
        float fy = __fadd_rn(acc[2 * cl],     b[2 * c]);
        float fx = __fadd_rn(acc[2 * cl + 1], b[2 * c + 1]);
        float f = __fadd_rn(__fadd_rn(__fmul_rn(fy, rely),
                                      __fmul_rn(fx, relx)),
                            __fmul_rn(phase_w[c], inv_s));
        float sv, cv;
        acc_sincosf(__fmul_rn(PI_F, f), sv, cv);
        g_x0[c * HW_HR + p]        = __fmul_rn(g_amp[c * HW_LR + q],        cv);
        g_x0[(c + 32) * HW_HR + p] = __fmul_rn(g_amp[(c + 32) * HW_LR + q], sv);
    }
}

// ---------------------------------------------------------------------------
// K3: per-pixel MLP, 2 threads per pixel (each owns 32 outputs per layer).
// Dot-product order per output unchanged (bit-identical to R13).
// ---------------------------------------------------------------------------
#define ROWSTR 132
#define K3_SMEM_BYTES ((3*4096 + 768 + 208 + 256*ROWSTR) * 4)

__global__ __launch_bounds__(512) void k_mlp(
    const float* __restrict__ w0, const float* __restrict__ b0,
    const float* __restrict__ w1, const float* __restrict__ b1,
    const float* __restrict__ w2, const float* __restrict__ b2,
    const float* __restrict__ wo, const float* __restrict__ bo,
    float* __restrict__ out)
{
    extern __shared__ float sm[];
    float* s_w  = sm;
    float* s_wo = sm + 3 * 4096;
    float* s_b  = s_wo + 768;
    float* s_px = s_b + 208;

    const int tid = threadIdx.x;
    const int pix = tid & 255, half = tid >> 8;
    for (int i = tid; i < 4096; i += 512) {
        s_w[i] = w0[i]; s_w[4096 + i] = w1[i]; s_w[8192 + i] = w2[i];
    }
    for (int i = tid; i < 768; i += 512) s_wo[i] = wo[i];
    if (tid < 64) { s_b[tid] = b0[tid]; s_b[64 + tid] = b1[tid]; s_b[128 + tid] = b2[tid]; }
    if (tid < 12) s_b[192 + tid] = bo[tid];

    const int p = blockIdx.x * 256 + pix;
    float* row = s_px + pix * ROWSTR;

    // split the x load across the two halves
    for (int c = half * 32; c < half * 32 + 32; c++)
        row[c] = g_x0[c * HW_HR + p];
    __syncthreads();

    int xo = 0;
#pragma unroll
    for (int L = 0; L < 3; L++) {
        const float* wl = s_w + L * 4096;
        const float* bl = s_b + L * 64;
        int yo = 64 - xo;
        const float4* xr = (const float4*)(row + xo);
        for (int ob = 0; ob < 4; ob++) {              // 4 blocks of 8 per half
            int out_base = half * 32 + ob * 8;
            float a[8];
#pragma unroll
            for (int oo = 0; oo < 8; oo++) a[oo] = bl[out_base + oo];
            const float* wb = wl + out_base * 64;
#pragma unroll
            for (int ch = 0; ch < 4; ch++) {
                float4 xv0 = xr[ch * 4 + 0], xv1 = xr[ch * 4 + 1];
                float4 xv2 = xr[ch * 4 + 2], xv3 = xr[ch * 4 + 3];
#pragma unroll
                for (int oo = 0; oo < 8; oo++) {
                    const float4* wp = (const float4*)(wb + oo * 64 + ch * 16);
                    float4 wq0 = wp[0], wq1 = wp[1], wq2 = wp[2], wq3 = wp[3];
                    float t = a[oo];
                    t = __fmaf_rn(wq0.x, xv0.x, t); t = __fmaf_rn(wq0.y, xv0.y, t);
                    t = __fmaf_rn(wq0.z, xv0.z, t); t = __fmaf_rn(wq0.w, xv0.w, t);
                    t = __fmaf_rn(wq1.x, xv1.x, t); t = __fmaf_rn(wq1.y, xv1.y, t);
                    t = __fmaf_rn(wq1.z, xv1.z, t); t = __fmaf_rn(wq1.w, xv1.w, t);
                    t = __fmaf_rn(wq2.x, xv2.x, t); t = __fmaf_rn(wq2.y, xv2.y, t);
                    t = __fmaf_rn(wq2.z, xv2.z, t); t = __fmaf_rn(wq2.w, xv2.w, t);
                    t = __fmaf_rn(wq3.x, xv3.x, t); t = __fmaf_rn(wq3.y, xv3.y, t);
                    t = __fmaf_rn(wq3.z, xv3.z, t); t = __fmaf_rn(wq3.w, xv3.w, t);
                    a[oo] = t;
                }
            }
#pragma unroll
            for (int oo = 0; oo < 8; oo++)
                row[yo + out_base + oo] = acc_sinf(__fmul_rn(30.0f, a[oo]));
        }
        xo = yo;
        __syncthreads();
    }

    // output layer 64 -> 12, split 6 + 6
    const float4* xr = (const float4*)(row + xo);
    for (int o = half * 6; o < half * 6 + 6; o++) {
        float acc = s_b[192 + o];
        const float4* wp = (const float4*)(s_wo + o * 64);
#pragma unroll
        for (int qq = 0; qq < 16; qq++) {
            float4 wv = wp[qq];
            float4 xv = xr[qq];
            acc = __fmaf_rn(wv.x, xv.x, acc); acc = __fmaf_rn(wv.y, xv.y, acc);
            acc = __fmaf_rn(wv.z, xv.z, acc); acc = __fmaf_rn(wv.w, xv.w, acc);
        }
        out[o * HW_HR + p] = acc;
    }
}

// ---------------------------------------------------------------------------
extern "C" void kernel_launch(void* const* d_in, const int* in_sizes, int n_in,
                              void* d_out, int out_size)
{
    const float* lr_feat = (const float*)d_in[0];
    const float* gb_feat = (const float*)d_in[1];
    const float* amp_w   = (const float*)d_in[2];
    const float* amp_b   = (const float*)d_in[3];
    const float* freq_w  = (const float*)d_in[4];
    const float* freq_b  = (const float*)d_in[5];
    const float* phase_w = (const float*)d_in[6];
    const float* w0      = (const float*)d_in[7];
    const float* b0      = (const float*)d_in[8];
    const float* w1      = (const float*)d_in[9];
    const float* b1      = (const float*)d_in[10];
    const float* w2      = (const float*)d_in[11];
    const float* b2      = (const float*)d_in[12];
    const float* wo      = (const float*)d_in[13];
    const float* bo      = (const float*)d_in[14];
    const void*  upf     = d_in[15];

    cudaFuncSetAttribute(k_mlp, cudaFuncAttributeMaxDynamicSharedMemorySize,
                         K3_SMEM_BYTES);

    k_conv_lr<<<dim3(LR_W / 32, LR_H / 4), 256>>>(lr_feat, amp_w, amp_b);
    k_freq_hr<<<dim3(HR_W / 32, HR_H / 4), 256>>>(gb_feat, freq_w, freq_b,
                                                  phase_w, upf);
    k_mlp<<<HW_HR / 256, 512, K3_SMEM_BYTES>>>(w0, b0, w1, b1, w2, b2, wo, bo,
                                               (float*)d_out);
}

// round 16
// speedup vs baseline: 1.2952x; 1.0584x over previous
#include <cuda_runtime.h>
#include <math.h>
#include <stdint.h>

#define LR_H 360
#define LR_W 640
#define HR_H 720
#define HR_W 1280
#define HW_LR (LR_H*LR_W)
#define HW_HR (HR_H*HR_W)

typedef unsigned long long u64;

// Scratch (allocation-free rule: __device__ globals)
__device__ float g_amp[64 * HW_LR];   // LR amplitude conv output (with bias)
__device__ float g_x0 [64 * HW_HR];   // up_amp * fourier (MLP input)

// ---------------------------------------------------------------------------
// f32x2 packed helpers (sm_100+). Each component is an IEEE fp32 op.
// ---------------------------------------------------------------------------
__device__ __forceinline__ u64 pack2(float lo, float hi) {
    u64 r; asm("mov.b64 %0, {%1, %2};" : "=l"(r) : "f"(lo), "f"(hi)); return r;
}
__device__ __forceinline__ void unpack2(u64 v, float& lo, float& hi) {
    asm("mov.b64 {%0, %1}, %2;" : "=f"(lo), "=f"(hi) : "l"(v));
}
__device__ __forceinline__ u64 fma2(u64 a, u64 b, u64 c) {
    u64 d; asm("fma.rn.f32x2 %0, %1, %2, %3;" : "=l"(d) : "l"(a), "l"(b), "l"(c));
    return d;
}

// ---------------------------------------------------------------------------
// Accurate sin/cos: Cody-Waite 3-constant pi/2 reduction + cephes minimax.
// ---------------------------------------------------------------------------
__device__ __forceinline__ void red_quad(float x, float& r, int& q) {
    float j = rintf(__fmul_rn(x, 0.636619772367581343f));
    float t = __fmaf_rn(j, -1.57079625129699707031f, x);
    t = __fmaf_rn(j, -7.54978941586015625e-8f, t);
    t = __fmaf_rn(j, -5.39030252995776476554e-15f, t);
    r = t;
    q = ((int)j) & 3;
}
__device__ __forceinline__ float sin_poly(float r, float z) {
    float p = __fmaf_rn(z, -1.9515295891e-4f, 8.3321608736e-3f);
    p = __fmaf_rn(z, p, -1.6666654611e-1f);
    return __fmaf_rn(__fmul_rn(z, r), p, r);
}
__device__ __forceinline__ float cos_poly(float z) {
    float p = __fmaf_rn(z, 2.443315711809948e-5f, -1.388731625493765e-3f);
    p = __fmaf_rn(z, p, 4.166664568298827e-2f);
    return __fmaf_rn(__fmul_rn(z, z), p, __fmaf_rn(z, -0.5f, 1.0f));
}
__device__ __forceinline__ float acc_sinf(float x) {
    float r; int q;
    red_quad(x, r, q);
    float z = __fmul_rn(r, r);
    float sr = sin_poly(r, z), cr = cos_poly(z);
    float v = ((q & 1) == 0) ? sr : cr;
    return ((q & 2) == 0) ? v : -v;
}
__device__ __forceinline__ void acc_sincosf(float x, float& s, float& c) {
    float r; int q;
    red_quad(x, r, q);
    float z = __fmul_rn(r, r);
    float sr = sin_poly(r, z), cr = cos_poly(z);
    float ss, cc;
    if ((q & 1) == 0) { ss = sr; cc = cr; } else { ss = cr; cc = -sr; }
    if (q & 2) { ss = -ss; cc = -cc; }
    s = ss; c = cc;
}

// ---------------------------------------------------------------------------
// K1: LR 3x3 conv 32->64 (+bias) -> g_amp.  f32x2: 2 co's packed per lane.
// Thread = (pixel in 32x4 tile, co-half h). acc2[16] = co pairs h*16..h*16+15.
// Per-component accumulation order identical to scalar version.
// ---------------------------------------------------------------------------
__global__ __launch_bounds__(256, 3) void k_conv_lr(
    const float* __restrict__ x, const float* __restrict__ w,
    const float* __restrict__ b)
{
    __shared__ float s_t[8 * 6 * 34];     // 8 ci x (4+2) rows x (32+2) cols
    __shared__ u64   s_wp[8 * 32 * 10];   // [ci][cp][k(9,pad10)] packed co pairs
    const int tid = threadIdx.x;
    const int tx = tid & 31, ty = (tid >> 5) & 3, h = tid >> 7;
    const int bx = blockIdx.x * 32, by = blockIdx.y * 4;

    u64 acc2[16];
#pragma unroll
    for (int i = 0; i < 16; i++) acc2[i] = 0ULL;

    for (int c0 = 0; c0 < 32; c0 += 8) {
        __syncthreads();
        for (int i = tid; i < 8 * 6 * 34; i += 256) {
            int ci = i / 204, rem = i - ci * 204, r = rem / 34, c = rem - r * 34;
            int yy = by + r - 1, xx = bx + c - 1;
            float v = 0.f;
            if (yy >= 0 && yy < LR_H && xx >= 0 && xx < LR_W)
                v = x[(c0 + ci) * HW_LR + yy * LR_W + xx];
            s_t[i] = v;
        }
        for (int i = tid; i < 8 * 32 * 9; i += 256) {
            int ci = i / 288, r = i - ci * 288, cp = r / 9, k = r - cp * 9;
            float lo = w[((2 * cp)     * 32 + c0 + ci) * 9 + k];
            float hi = w[((2 * cp + 1) * 32 + c0 + ci) * 9 + k];
            s_wp[(ci * 32 + cp) * 10 + k] = pack2(lo, hi);
        }
        __syncthreads();
        for (int ci = 0; ci < 8; ci++) {
            const float* tp = &s_t[ci * 204 + ty * 34 + tx];
            u64 v0 = pack2(tp[0],  tp[0]),  v1 = pack2(tp[1],  tp[1]);
            u64 v2 = pack2(tp[2],  tp[2]),  v3 = pack2(tp[34], tp[34]);
            u64 v4 = pack2(tp[35], tp[35]), v5 = pack2(tp[36], tp[36]);
            u64 v6 = pack2(tp[68], tp[68]), v7 = pack2(tp[69], tp[69]);
            u64 v8 = pack2(tp[70], tp[70]);
            const u64* wpb = &s_wp[(ci * 32 + h * 16) * 10];
#pragma unroll
            for (int cp = 0; cp < 16; cp++) {
                const u64* wp = wpb + cp * 10;
                ulonglong2 wA = *(const ulonglong2*)(wp + 0);
                ulonglong2 wB = *(const ulonglong2*)(wp + 2);
                ulonglong2 wC = *(const ulonglong2*)(wp + 4);
                ulonglong2 wD = *(const ulonglong2*)(wp + 6);
                u64 w8 = wp[8];
                u64 a = acc2[cp];
                a = fma2(wA.x, v0, a); a = fma2(wA.y, v1, a);
                a = fma2(wB.x, v2, a); a = fma2(wB.y, v3, a);
                a = fma2(wC.x, v4, a); a = fma2(wC.y, v5, a);
                a = fma2(wD.x, v6, a); a = fma2(wD.y, v7, a);
                a = fma2(w8,   v8, a);
                acc2[cp] = a;
            }
        }
    }
    int p = (by + ty) * LR_W + bx + tx;
#pragma unroll
    for (int cp = 0; cp < 16; cp++) {
        float lo, hi;
        unpack2(acc2[cp], lo, hi);
        int co = 2 * (h * 16 + cp);
        g_amp[co * HW_LR + p]       = __fadd_rn(lo, b[co]);
        g_amp[(co + 1) * HW_LR + p] = __fadd_rn(hi, b[co + 1]);
    }
}

// ---------------------------------------------------------------------------
// K2: HR 3x3 conv (f32x2 packed) -> f -> fourier*up_amp -> g_x0.
// acc2[cl] = (fy, fx) channel pair c = h*16+cl directly.
// Grid math: XLA reciprocal-multiply rewrite (VALIDATED R12), verbatim.
// ---------------------------------------------------------------------------
__global__ __launch_bounds__(256, 3) void k_freq_hr(
    const float* __restrict__ x, const float* __restrict__ w,
    const float* __restrict__ b, const float* __restrict__ phase_w,
    const void* __restrict__ upf)
{
    __shared__ float s_t[8 * 6 * 34];
    __shared__ u64   s_wp[8 * 32 * 10];
    const int tid = threadIdx.x;
    const int tx = tid & 31, ty = (tid >> 5) & 3, h = tid >> 7;
    const int bx = blockIdx.x * 32, by = blockIdx.y * 4;

    u64 acc2[16];
#pragma unroll
    for (int i = 0; i < 16; i++) acc2[i] = 0ULL;

    for (int c0 = 0; c0 < 32; c0 += 8) {
        __syncthreads();
        for (int i = tid; i < 8 * 6 * 34; i += 256) {
            int ci = i / 204, rem = i - ci * 204, r = rem / 34, c = rem - r * 34;
            int yy = by + r - 1, xx = bx + c - 1;
            float v = 0.f;
            if (yy >= 0 && yy < HR_H && xx >= 0 && xx < HR_W)
                v = x[(c0 + ci) * HW_HR + yy * HR_W + xx];
            s_t[i] = v;
        }
        for (int i = tid; i < 8 * 32 * 9; i += 256) {
            int ci = i / 288, r = i - ci * 288, cp = r / 9, k = r - cp * 9;
            float lo = w[((2 * cp)     * 32 + c0 + ci) * 9 + k];
            float hi = w[((2 * cp + 1) * 32 + c0 + ci) * 9 + k];
            s_wp[(ci * 32 + cp) * 10 + k] = pack2(lo, hi);
        }
        __syncthreads();
        for (int ci = 0; ci < 8; ci++) {
            const float* tp = &s_t[ci * 204 + ty * 34 + tx];
            u64 v0 = pack2(tp[0],  tp[0]),  v1 = pack2(tp[1],  tp[1]);
            u64 v2 = pack2(tp[2],  tp[2]),  v3 = pack2(tp[34], tp[34]);
            u64 v4 = pack2(tp[35], tp[35]), v5 = pack2(tp[36], tp[36]);
            u64 v6 = pack2(tp[68], tp[68]), v7 = pack2(tp[69], tp[69]);
            u64 v8 = pack2(tp[70], tp[70]);
            const u64* wpb = &s_wp[(ci * 32 + h * 16) * 10];
#pragma unroll
            for (int cp = 0; cp < 16; cp++) {
                const u64* wp = wpb + cp * 10;
                ulonglong2 wA = *(const ulonglong2*)(wp + 0);
                ulonglong2 wB = *(const ulonglong2*)(wp + 2);
                ulonglong2 wC = *(const ulonglong2*)(wp + 4);
                ulonglong2 wD = *(const ulonglong2*)(wp + 6);
                u64 w8 = wp[8];
                u64 a = acc2[cp];
                a = fma2(wA.x, v0, a); a = fma2(wA.y, v1, a);
                a = fma2(wB.x, v2, a); a = fma2(wB.y, v3, a);
                a = fma2(wC.x, v4, a); a = fma2(wC.y, v5, a);
                a = fma2(wD.x, v6, a); a = fma2(wD.y, v7, a);
                a = fma2(w8,   v8, a);
                acc2[cp] = a;
            }
        }
    }

    // --- XLA-style fp32 grid math with x/c -> x*(1/c) rewrite (R12) ---
    const int gx = bx + tx, gy = by + ty;
    const float R720  = (float)(1.0 / 720.0);
    const float R1280 = (float)(1.0 / 1280.0);
    const float R360  = (float)(1.0 / 360.0);
    const float R640  = (float)(1.0 / 640.0);

    float gyf = __fadd_rn(__fmul_rn(__fmul_rn(__fadd_rn((float)gy, 0.5f), R720),
                                    2.0f), -1.0f);
    float gxf = __fadd_rn(__fmul_rn(__fmul_rn(__fadd_rn((float)gx, 0.5f), R1280),
                                    2.0f), -1.0f);
    const int iy = gy >> 1, ix = gx >> 1;
    float qy = __fadd_rn(__fmul_rn(__fmul_rn(__fadd_rn((float)iy, 0.5f), R360),
                                   2.0f), -1.0f);
    float qx = __fadd_rn(__fmul_rn(__fmul_rn(__fadd_rn((float)ix, 0.5f), R640),
                                   2.0f), -1.0f);
    float rely = __fmul_rn(__fsub_rn(gyf, qy), (float)LR_H);
    float relx = __fmul_rn(__fsub_rn(gxf, qx), (float)LR_W);

    const int q = iy * LR_W + ix;
    const int p = gy * HR_W + gx;

    int iv = *(const int*)upf;
    float s_up = (iv > 0 && iv < 100000) ? (float)iv : __int_as_float(iv);
    float inv_s = __fdiv_rn(1.0f, s_up);
    const float PI_F = 3.14159265358979323846f;

#pragma unroll
    for (int cl = 0; cl < 16; cl++) {
        int c = h * 16 + cl;
        float ay, ax;
        unpack2(acc2[cl], ay, ax);
        float fy = __fadd_rn(ay, b[2 * c]);
        float fx = __fadd_rn(ax, b[2 * c + 1]);
        float f = __fadd_rn(__fadd_rn(__fmul_rn(fy, rely),
                                      __fmul_rn(fx, relx)),
                            __fmul_rn(phase_w[c], inv_s));
        float sv, cv;
        acc_sincosf(__fmul_rn(PI_F, f), sv, cv);
        g_x0[c * HW_HR + p]        = __fmul_rn(g_amp[c * HW_LR + q],        cv);
        g_x0[(c + 32) * HW_HR + p] = __fmul_rn(g_amp[(c + 32) * HW_LR + q], sv);
    }
}

// ---------------------------------------------------------------------------
// K3: per-pixel MLP, 2 threads per pixel; activations hoisted to registers
// per layer (numerics unchanged, bit-identical to R15).
// ---------------------------------------------------------------------------
#define ROWSTR 132
#define K3_SMEM_BYTES ((3*4096 + 768 + 208 + 256*ROWSTR) * 4)

__global__ __launch_bounds__(512) void k_mlp(
    const float* __restrict__ w0, const float* __restrict__ b0,
    const float* __restrict__ w1, const float* __restrict__ b1,
    const float* __restrict__ w2, const float* __restrict__ b2,
    const float* __restrict__ wo, const float* __restrict__ bo,
    float* __restrict__ out)
{
    extern __shared__ float sm[];
    float* s_w  = sm;
    float* s_wo = sm + 3 * 4096;
    float* s_b  = s_wo + 768;
    float* s_px = s_b + 208;

    const int tid = threadIdx.x;
    const int pix = tid & 255, half = tid >> 8;
    for (int i = tid; i < 4096; i += 512) {
        s_w[i] = w0[i]; s_w[4096 + i] = w1[i]; s_w[8192 + i] = w2[i];
    }
    for (int i = tid; i < 768; i += 512) s_wo[i] = wo[i];
    if (tid < 64) { s_b[tid] = b0[tid]; s_b[64 + tid] = b1[tid]; s_b[128 + tid] = b2[tid]; }
    if (tid < 12) s_b[192 + tid] = bo[tid];

    const int p = blockIdx.x * 256 + pix;
    float* row = s_px + pix * ROWSTR;

    for (int c = half * 32; c < half * 32 + 32; c++)
        row[c] = g_x0[c * HW_HR + p];
    __syncthreads();

    int xo = 0;
#pragma unroll
    for (int L = 0; L < 3; L++) {
        const float* wl = s_w + L * 4096;
        const float* bl = s_b + L * 64;
        int yo = 64 - xo;
        const float4* xr = (const float4*)(row + xo);
        float4 xv[16];
#pragma unroll
        for (int j = 0; j < 16; j++) xv[j] = xr[j];
        for (int ob = 0; ob < 4; ob++) {
            int out_base = half * 32 + ob * 8;
            float a[8];
#pragma unroll
            for (int oo = 0; oo < 8; oo++) a[oo] = bl[out_base + oo];
            const float* wb = wl + out_base * 64;
#pragma unroll
            for (int ch = 0; ch < 4; ch++) {
                float4 xv0 = xv[ch * 4 + 0], xv1 = xv[ch * 4 + 1];
                float4 xv2 = xv[ch * 4 + 2], xv3 = xv[ch * 4 + 3];
#pragma unroll
                for (int oo = 0; oo < 8; oo++) {
                    const float4* wp = (const float4*)(wb + oo * 64 + ch * 16);
                    float4 wq0 = wp[0], wq1 = wp[1], wq2 = wp[2], wq3 = wp[3];
                    float t = a[oo];
                    t = __fmaf_rn(wq0.x, xv0.x, t); t = __fmaf_rn(wq0.y, xv0.y, t);
                    t = __fmaf_rn(wq0.z, xv0.z, t); t = __fmaf_rn(wq0.w, xv0.w, t);
                    t = __fmaf_rn(wq1.x, xv1.x, t); t = __fmaf_rn(wq1.y, xv1.y, t);
                    t = __fmaf_rn(wq1.z, xv1.z, t); t = __fmaf_rn(wq1.w, xv1.w, t);
                    t = __fmaf_rn(wq2.x, xv2.x, t); t = __fmaf_rn(wq2.y, xv2.y, t);
                    t = __fmaf_rn(wq2.z, xv2.z, t); t = __fmaf_rn(wq2.w, xv2.w, t);
                    t = __fmaf_rn(wq3.x, xv3.x, t); t = __fmaf_rn(wq3.y, xv3.y, t);
                    t = __fmaf_rn(wq3.z, xv3.z, t); t = __fmaf_rn(wq3.w, xv3.w, t);
                    a[oo] = t;
                }
            }
#pragma unroll
            for (int oo = 0; oo < 8; oo++)
                row[yo + out_base + oo] = acc_sinf(__fmul_rn(30.0f, a[oo]));
        }
        xo = yo;
        __syncthreads();
    }

    const float4* xr = (const float4*)(row + xo);
    for (int o = half * 6; o < half * 6 + 6; o++) {
        float acc = s_b[192 + o];
        const float4* wp = (const float4*)(s_wo + o * 64);
#pragma unroll
        for (int qq = 0; qq < 16; qq++) {
            float4 wv = wp[qq];
            float4 xv = xr[qq];
            acc = __fmaf_rn(wv.x, xv.x, acc); acc = __fmaf_rn(wv.y, xv.y, acc);
            acc = __fmaf_rn(wv.z, xv.z, acc); acc = __fmaf_rn(wv.w, xv.w, acc);
        }
        out[o * HW_HR + p] = acc;
    }
}

// ---------------------------------------------------------------------------
extern "C" void kernel_launch(void* const* d_in, const int* in_sizes, int n_in,
                              void* d_out, int out_size)
{
    const float* lr_feat = (const float*)d_in[0];
    const float* gb_feat = (const float*)d_in[1];
    const float* amp_w   = (const float*)d_in[2];
    const float* amp_b   = (const float*)d_in[3];
    const float* freq_w  = (const float*)d_in[4];
    const float* freq_b  = (const float*)d_in[5];
    const float* phase_w = (const float*)d_in[6];
    const float* w0      = (const float*)d_in[7];
    const float* b0      = (const float*)d_in[8];
    const float* w1      = (const float*)d_in[9];
    const float* b1      = (const float*)d_in[10];
    const float* w2      = (const float*)d_in[11];
    const float* b2      = (const float*)d_in[12];
    const float* wo      = (const float*)d_in[13];
    const float* bo      = (const float*)d_in[14];
    const void*  upf     = d_in[15];

    cudaFuncSetAttribute(k_mlp, cudaFuncAttributeMaxDynamicSharedMemorySize,
                         K3_SMEM_BYTES);

    k_conv_lr<<<dim3(LR_W / 32, LR_H / 4), 256>>>(lr_feat, amp_w, amp_b);
    k_freq_hr<<<dim3(HR_W / 32, HR_H / 4), 256>>>(gb_feat, freq_w, freq_b,
                                                  phase_w, upf);
    k_mlp<<<HW_HR / 256, 512, K3_SMEM_BYTES>>>(w0, b0, w1, b1, w2, b2, wo, bo,
                                               (float*)d_out);
}

// round 17
// speedup vs baseline: 1.5972x; 1.2332x over previous
#include <cuda_runtime.h>
#include <math.h>
#include <stdint.h>

#define LR_H 360
#define LR_W 640
#define HR_H 720
#define HR_W 1280
#define HW_LR (LR_H*LR_W)
#define HW_HR (HR_H*HR_W)

typedef unsigned long long u64;

// Scratch (allocation-free rule: __device__ globals)
__device__ float g_amp[64 * HW_LR];   // LR amplitude conv output (with bias)
__device__ float g_x0 [64 * HW_HR];   // up_amp * fourier (MLP input)

// ---------------------------------------------------------------------------
// f32x2 packed helpers (sm_100+). Each component is an IEEE fp32 op.
// ---------------------------------------------------------------------------
__device__ __forceinline__ u64 pack2(float lo, float hi) {
    u64 r; asm("mov.b64 %0, {%1, %2};" : "=l"(r) : "f"(lo), "f"(hi)); return r;
}
__device__ __forceinline__ u64 dup2(float v) {
    u64 r; asm("mov.b64 %0, {%1, %1};" : "=l"(r) : "f"(v)); return r;
}
__device__ __forceinline__ void unpack2(u64 v, float& lo, float& hi) {
    asm("mov.b64 {%0, %1}, %2;" : "=f"(lo), "=f"(hi) : "l"(v));
}
__device__ __forceinline__ u64 fma2(u64 a, u64 b, u64 c) {
    u64 d; asm("fma.rn.f32x2 %0, %1, %2, %3;" : "=l"(d) : "l"(a), "l"(b), "l"(c));
    return d;
}

// ---------------------------------------------------------------------------
// Accurate sin/cos: Cody-Waite 3-constant pi/2 reduction + cephes minimax.
// ---------------------------------------------------------------------------
__device__ __forceinline__ void red_quad(float x, float& r, int& q) {
    float j = rintf(__fmul_rn(x, 0.636619772367581343f));
    float t = __fmaf_rn(j, -1.57079625129699707031f, x);
    t = __fmaf_rn(j, -7.54978941586015625e-8f, t);
    t = __fmaf_rn(j, -5.39030252995776476554e-15f, t);
    r = t;
    q = ((int)j) & 3;
}
__device__ __forceinline__ float sin_poly(float r, float z) {
    float p = __fmaf_rn(z, -1.9515295891e-4f, 8.3321608736e-3f);
    p = __fmaf_rn(z, p, -1.6666654611e-1f);
    return __fmaf_rn(__fmul_rn(z, r), p, r);
}
__device__ __forceinline__ float cos_poly(float z) {
    float p = __fmaf_rn(z, 2.443315711809948e-5f, -1.388731625493765e-3f);
    p = __fmaf_rn(z, p, 4.166664568298827e-2f);
    return __fmaf_rn(__fmul_rn(z, z), p, __fmaf_rn(z, -0.5f, 1.0f));
}
__device__ __forceinline__ float acc_sinf(float x) {
    float r; int q;
    red_quad(x, r, q);
    float z = __fmul_rn(r, r);
    float sr = sin_poly(r, z), cr = cos_poly(z);
    float v = ((q & 1) == 0) ? sr : cr;
    return ((q & 2) == 0) ? v : -v;
}
__device__ __forceinline__ void acc_sincosf(float x, float& s, float& c) {
    float r; int q;
    red_quad(x, r, q);
    float z = __fmul_rn(r, r);
    float sr = sin_poly(r, z), cr = cos_poly(z);
    float ss, cc;
    if ((q & 1) == 0) { ss = sr; cc = cr; } else { ss = cr; cc = -sr; }
    if (q & 2) { ss = -ss; cc = -cc; }
    s = ss; c = cc;
}

// ---------------------------------------------------------------------------
// Conv core shared by K1/K2: 32x8 pixel tile, thread = (tx, ty(2), h(4));
// each thread: 4 pixel rows (ty*4+r), 8 co-pairs (h*8+cp).
// acc2[r][cp], per-component FMA order identical to scalar reference order.
// ---------------------------------------------------------------------------
#define CONV_BODY(H_, W_, HW_)                                                 \
    __shared__ float s_t[8 * 10 * 34];                                         \
    __shared__ u64   s_wp[8 * 32 * 10];                                        \
    const int tid = threadIdx.x;                                               \
    const int tx = tid & 31, ty = (tid >> 5) & 1, h = tid >> 6;                \
    const int bx = blockIdx.x * 32, by = blockIdx.y * 8;                       \
    u64 acc2[4][8];                                                            \
    _Pragma("unroll")                                                          \
    for (int r = 0; r < 4; r++)                                                \
        _Pragma("unroll")                                                      \
        for (int cp = 0; cp < 8; cp++) acc2[r][cp] = 0ULL;                     \
    for (int c0 = 0; c0 < 32; c0 += 8) {                                       \
        __syncthreads();                                                       \
        for (int i = tid; i < 8 * 10 * 34; i += 256) {                         \
            int ci = i / 340, rem = i - ci * 340, r = rem / 34, c = rem - r * 34; \
            int yy = by + r - 1, xx = bx + c - 1;                              \
            float v = 0.f;                                                     \
            if (yy >= 0 && yy < H_ && xx >= 0 && xx < W_)                      \
                v = x[(c0 + ci) * HW_ + yy * W_ + xx];                         \
            s_t[i] = v;                                                        \
        }                                                                      \
        for (int i = tid; i < 8 * 32 * 9; i += 256) {                          \
            int ci = i / 288, rr = i - ci * 288, cp = rr / 9, k = rr - cp * 9; \
            float lo = w[((2 * cp)     * 32 + c0 + ci) * 9 + k];               \
            float hi = w[((2 * cp + 1) * 32 + c0 + ci) * 9 + k];               \
            s_wp[(ci * 32 + cp) * 10 + k] = pack2(lo, hi);                     \
        }                                                                      \
        __syncthreads();                                                       \
        for (int ci = 0; ci < 8; ci++) {                                       \
            const float* tp = &s_t[ci * 340 + (ty * 4) * 34 + tx];             \
            u64 vv[6][3];                                                      \
            _Pragma("unroll")                                                  \
            for (int t = 0; t < 6; t++)                                        \
                _Pragma("unroll")                                              \
                for (int c = 0; c < 3; c++)                                    \
                    vv[t][c] = dup2(tp[t * 34 + c]);                           \
            const u64* wpb = &s_wp[(ci * 32 + h * 8) * 10];                    \
            _Pragma("unroll")                                                  \
            for (int cp = 0; cp < 8; cp++) {                                   \
                const u64* wp = wpb + cp * 10;                                 \
                ulonglong2 wA = *(const ulonglong2*)(wp + 0);                  \
                ulonglong2 wB = *(const ulonglong2*)(wp + 2);                  \
                ulonglong2 wC = *(const ulonglong2*)(wp + 4);                  \
                ulonglong2 wD = *(const ulonglong2*)(wp + 6);                  \
                u64 w8 = wp[8];                                                \
                _Pragma("unroll")                                              \
                for (int r = 0; r < 4; r++) {                                  \
                    u64 a = acc2[r][cp];                                       \
                    a = fma2(wA.x, vv[r][0], a);                               \
                    a = fma2(wA.y, vv[r][1], a);                               \
                    a = fma2(wB.x, vv[r][2], a);                               \
                    a = fma2(wB.y, vv[r + 1][0], a);                           \
                    a = fma2(wC.x, vv[r + 1][1], a);                           \
                    a = fma2(wC.y, vv[r + 1][2], a);                           \
                    a = fma2(wD.x, vv[r + 2][0], a);                           \
                    a = fma2(wD.y, vv[r + 2][1], a);                           \
                    a = fma2(w8,   vv[r + 2][2], a);                           \
                    acc2[r][cp] = a;                                           \
                }                                                              \
            }                                                                  \
        }                                                                      \
    }

// ---------------------------------------------------------------------------
// K1: LR 3x3 conv 32->64 (+bias) -> g_amp
// ---------------------------------------------------------------------------
__global__ __launch_bounds__(256, 2) void k_conv_lr(
    const float* __restrict__ x, const float* __restrict__ w,
    const float* __restrict__ b)
{
    CONV_BODY(LR_H, LR_W, HW_LR)

#pragma unroll
    for (int r = 0; r < 4; r++) {
        int p = (by + ty * 4 + r) * LR_W + bx + tx;
#pragma unroll
        for (int cp = 0; cp < 8; cp++) {
            float lo, hi;
            unpack2(acc2[r][cp], lo, hi);
            int co = 2 * (h * 8 + cp);
            g_amp[co * HW_LR + p]       = __fadd_rn(lo, b[co]);
            g_amp[(co + 1) * HW_LR + p] = __fadd_rn(hi, b[co + 1]);
        }
    }
}

// ---------------------------------------------------------------------------
// K2: HR 3x3 conv -> f -> fourier*up_amp -> g_x0.
// Thread epilogue: 4 pixels x 8 channel pairs (c = h*8+cp).
// Grid math: XLA reciprocal-multiply rewrite (VALIDATED R12), verbatim.
// ---------------------------------------------------------------------------
__global__ __launch_bounds__(256, 2) void k_freq_hr(
    const float* __restrict__ x, const float* __restrict__ w,
    const float* __restrict__ b, const float* __restrict__ phase_w,
    const void* __restrict__ upf)
{
    CONV_BODY(HR_H, HR_W, HW_HR)

    const float R720  = (float)(1.0 / 720.0);
    const float R1280 = (float)(1.0 / 1280.0);
    const float R360  = (float)(1.0 / 360.0);
    const float R640  = (float)(1.0 / 640.0);

    int iv = *(const int*)upf;
    float s_up = (iv > 0 && iv < 100000) ? (float)iv : __int_as_float(iv);
    float inv_s = __fdiv_rn(1.0f, s_up);
    const float PI_F = 3.14159265358979323846f;

    const int gx = bx + tx;
    float gxf = __fadd_rn(__fmul_rn(__fmul_rn(__fadd_rn((float)gx, 0.5f), R1280),
                                    2.0f), -1.0f);
    const int ix = gx >> 1;
    float qx = __fadd_rn(__fmul_rn(__fmul_rn(__fadd_rn((float)ix, 0.5f), R640),
                                   2.0f), -1.0f);
    float relx = __fmul_rn(__fsub_rn(gxf, qx), (float)LR_W);

#pragma unroll
    for (int r = 0; r < 4; r++) {
        const int gy = by + ty * 4 + r;
        float gyf = __fadd_rn(__fmul_rn(__fmul_rn(__fadd_rn((float)gy, 0.5f), R720),
                                        2.0f), -1.0f);
        const int iy = gy >> 1;
        float qy = __fadd_rn(__fmul_rn(__fmul_rn(__fadd_rn((float)iy, 0.5f), R360),
                                       2.0f), -1.0f);
        float rely = __fmul_rn(__fsub_rn(gyf, qy), (float)LR_H);
        const int q = iy * LR_W + ix;
        const int p = gy * HR_W + gx;

#pragma unroll
        for (int cp = 0; cp < 8; cp++) {
            int c = h * 8 + cp;
            float ay, ax2;
            unpack2(acc2[r][cp], ay, ax2);
            float fy = __fadd_rn(ay,  b[2 * c]);
            float fx = __fadd_rn(ax2, b[2 * c + 1]);
            float f = __fadd_rn(__fadd_rn(__fmul_rn(fy, rely),
                                          __fmul_rn(fx, relx)),
                                __fmul_rn(phase_w[c], inv_s));
            float sv, cv;
            acc_sincosf(__fmul_rn(PI_F, f), sv, cv);
            g_x0[c * HW_HR + p]        = __fmul_rn(g_amp[c * HW_LR + q],        cv);
            g_x0[(c + 32) * HW_HR + p] = __fmul_rn(g_amp[(c + 32) * HW_LR + q], sv);
        }
    }
}

// ---------------------------------------------------------------------------
// K3: per-pixel MLP, 2 threads/pixel, f32x2: 2 outputs packed per acc.
// Per-component dot order unchanged (bit-identical to R16).
// ---------------------------------------------------------------------------
#define ROWSTR 132
#define K3_SMEM_BYTES ((3*4096 + 768 + 208 + 256*ROWSTR) * 4)

__global__ __launch_bounds__(512) void k_mlp(
    const float* __restrict__ w0, const float* __restrict__ b0,
    const float* __restrict__ w1, const float* __restrict__ b1,
    const float* __restrict__ w2, const float* __restrict__ b2,
    const float* __restrict__ wo, const float* __restrict__ bo,
    float* __restrict__ out)
{
    extern __shared__ float sm[];
    u64*   s_w2 = (u64*)sm;              // 3*2048 packed output-pair weights
    float* s_wo = sm + 3 * 4096;         // 12*64 scalar
    float* s_b  = s_wo + 768;            // biases
    float* s_px = s_b + 208;             // 256 rows * 132

    const int tid = threadIdx.x;
    const int pix = tid & 255, half = tid >> 8;

    for (int i = tid; i < 2048; i += 512) {
        int po = i >> 6, ii = i & 63;
        s_w2[i]         = pack2(w0[(2 * po) * 64 + ii], w0[(2 * po + 1) * 64 + ii]);
        s_w2[2048 + i]  = pack2(w1[(2 * po) * 64 + ii], w1[(2 * po + 1) * 64 + ii]);
        s_w2[4096 + i]  = pack2(w2[(2 * po) * 64 + ii], w2[(2 * po + 1) * 64 + ii]);
    }
    for (int i = tid; i < 768; i += 512) s_wo[i] = wo[i];
    if (tid < 64) { s_b[tid] = b0[tid]; s_b[64 + tid] = b1[tid]; s_b[128 + tid] = b2[tid]; }
    if (tid < 12) s_b[192 + tid] = bo[tid];

    const int p = blockIdx.x * 256 + pix;
    float* row = s_px + pix * ROWSTR;

    for (int c = half * 32; c < half * 32 + 32; c++)
        row[c] = g_x0[c * HW_HR + p];
    __syncthreads();

    int xo = 0;
#pragma unroll
    for (int L = 0; L < 3; L++) {
        const u64* wl = s_w2 + L * 2048;
        const float* bl = s_b + L * 64;
        int yo = 64 - xo;
        const float* xrow = row + xo;

        u64 acc2[16];
#pragma unroll
        for (int po16 = 0; po16 < 16; po16++) {
            int po = half * 16 + po16;
            acc2[po16] = pack2(bl[2 * po], bl[2 * po + 1]);
        }
#pragma unroll
        for (int ch = 0; ch < 4; ch++) {
            u64 xp[16];
            const float4* xr4 = (const float4*)(xrow + ch * 16);
#pragma unroll
            for (int j = 0; j < 4; j++) {
                float4 xv = xr4[j];
                xp[j * 4 + 0] = dup2(xv.x); xp[j * 4 + 1] = dup2(xv.y);
                xp[j * 4 + 2] = dup2(xv.z); xp[j * 4 + 3] = dup2(xv.w);
            }
#pragma unroll
            for (int po16 = 0; po16 < 16; po16++) {
                const ulonglong2* wp =
                    (const ulonglong2*)(wl + (half * 16 + po16) * 64 + ch * 16);
                u64 a = acc2[po16];
#pragma unroll
                for (int j = 0; j < 8; j++) {
                    ulonglong2 wv = wp[j];
                    a = fma2(wv.x, xp[2 * j],     a);
                    a = fma2(wv.y, xp[2 * j + 1], a);
                }
                acc2[po16] = a;
            }
        }
#pragma unroll
        for (int po16 = 0; po16 < 16; po16++) {
            int po = half * 16 + po16;
            float e, o;
            unpack2(acc2[po16], e, o);
            row[yo + 2 * po]     = acc_sinf(__fmul_rn(30.0f, e));
            row[yo + 2 * po + 1] = acc_sinf(__fmul_rn(30.0f, o));
        }
        xo = yo;
        __syncthreads();
    }

    // output layer 64 -> 12, split 6 + 6 (scalar, unchanged)
    const float4* xr = (const float4*)(row + xo);
    for (int o = half * 6; o < half * 6 + 6; o++) {
        float acc = s_b[192 + o];
        const float4* wp = (const float4*)(s_wo + o * 64);
#pragma unroll
        for (int qq = 0; qq < 16; qq++) {
            float4 wv = wp[qq];
            float4 xv = xr[qq];
            acc = __fmaf_rn(wv.x, xv.x, acc); acc = __fmaf_rn(wv.y, xv.y, acc);
            acc = __fmaf_rn(wv.z, xv.z, acc); acc = __fmaf_rn(wv.w, xv.w, acc);
        }
        out[o * HW_HR + p] = acc;
    }
}

// ---------------------------------------------------------------------------
extern "C" void kernel_launch(void* const* d_in, const int* in_sizes, int n_in,
                              void* d_out, int out_size)
{
    const float* lr_feat = (const float*)d_in[0];
    const float* gb_feat = (const float*)d_in[1];
    const float* amp_w   = (const float*)d_in[2];
    const float* amp_b   = (const float*)d_in[3];
    const float* freq_w  = (const float*)d_in[4];
    const float* freq_b  = (const float*)d_in[5];
    const float* phase_w = (const float*)d_in[6];
    const float* w0      = (const float*)d_in[7];
    const float* b0      = (const float*)d_in[8];
    const float* w1      = (const float*)d_in[9];
    const float* b1      = (const float*)d_in[10];
    const float* w2      = (const float*)d_in[11];
    const float* b2      = (const float*)d_in[12];
    const float* wo      = (const float*)d_in[13];
    const float* bo      = (const float*)d_in[14];
    const void*  upf     = d_in[15];

    cudaFuncSetAttribute(k_mlp, cudaFuncAttributeMaxDynamicSharedMemorySize,
                         K3_SMEM_BYTES);

    k_conv_lr<<<dim3(LR_W / 32, LR_H / 8), 256>>>(lr_feat, amp_w, amp_b);
    k_freq_hr<<<dim3(HR_W / 32, HR_H / 8), 256>>>(gb_feat, freq_w, freq_b,
                                                  phase_w, upf);
    k_mlp<<<HW_HR / 256, 512, K3_SMEM_BYTES>>>(w0, b0, w1, b1, w2, b2, wo, bo,
                                               (float*)d_out);
}